// round 15
// baseline (speedup 1.0000x reference)
#include <cuda_runtime.h>
#include <cuda_bf16.h>
#include <math.h>
#include <cstdint>

// ---------------- problem constants ----------------
#define NN      10000
#define E0      80000
#define ETOT    (E0 + NN)
#define FIN     128
#define HID     300
#define H1      5
#define HC1     (H1*HID)       // 1500
#define H3      3
#define NCLS    40
#define HC3     (H3*NCLS)      // 120
#define HMAX    5
#define KPAD2   1536

// ---------------- static device scratch ----------------
__device__ __align__(16) float g_bufA[(size_t)NN * HC1];
__device__ __align__(16) float g_bufB[(size_t)NN * HC1];
__device__ __align__(16) float g_alpha[(size_t)ETOT * HMAX];
__device__ __align__(16) float g_asrc[NN * HMAX];
__device__ __align__(16) float g_adst[NN * HMAX];
__device__ __align__(16) float g_invs[NN * HMAX];
__device__ __align__(16) float g_out3[NN * NCLS];
__device__ float g_pooled[NCLS];
__device__ int   g_deg[NN];
__device__ int   g_off[NN + 1];
__device__ int   g_cur[NN];
__device__ int   g_csr_eid[ETOT];
__device__ int   g_src32[ETOT];
__device__ int   g_dst32[ETOT];
__device__ int   g_fmt;

__device__ __align__(16) __nv_bfloat16 g_Ah[(size_t)NN * KPAD2];
__device__ __align__(16) __nv_bfloat16 g_Al[(size_t)NN * KPAD2];
__device__ __align__(16) __nv_bfloat16 g_B1h[(size_t)HC1 * FIN];
__device__ __align__(16) __nv_bfloat16 g_B1l[(size_t)HC1 * FIN];
__device__ __align__(16) __nv_bfloat16 g_B2h[(size_t)HC1 * KPAD2];
__device__ __align__(16) __nv_bfloat16 g_B2l[(size_t)HC1 * KPAD2];
__device__ __align__(16) __nv_bfloat16 g_B3h[(size_t)HC3 * KPAD2];
__device__ __align__(16) __nv_bfloat16 g_B3l[(size_t)HC3 * KPAD2];

// ================= helpers =================
__device__ __forceinline__ uint32_t smem_u32(const void* p) {
    uint32_t a;
    asm("{ .reg .u64 t; cvta.to.shared.u64 t, %1; cvt.u32.u64 %0, t; }" : "=r"(a) : "l"(p));
    return a;
}
__device__ __forceinline__ void cp_async16(uint32_t dst, const void* src, int src_bytes) {
    asm volatile("cp.async.cg.shared.global [%0], [%1], 16, %2;"
                 :: "r"(dst), "l"(src), "r"(src_bytes) : "memory");
}
__device__ __forceinline__ void ldsm_x4(uint32_t& r0, uint32_t& r1, uint32_t& r2, uint32_t& r3,
                                        uint32_t addr) {
    asm volatile("ldmatrix.sync.aligned.m8n8.x4.shared.b16 {%0,%1,%2,%3}, [%4];"
                 : "=r"(r0), "=r"(r1), "=r"(r2), "=r"(r3) : "r"(addr));
}
__device__ __forceinline__ void mma_bf16(float* c, const uint32_t* a, const uint32_t* b) {
    asm volatile("mma.sync.aligned.m16n8k16.row.col.f32.bf16.bf16.f32 "
                 "{%0,%1,%2,%3}, {%4,%5,%6,%7}, {%8,%9}, {%0,%1,%2,%3};"
                 : "+f"(c[0]), "+f"(c[1]), "+f"(c[2]), "+f"(c[3])
                 : "r"(a[0]), "r"(a[1]), "r"(a[2]), "r"(a[3]), "r"(b[0]), "r"(b[1]));
}

// ---------------- graph construction ----------------
__global__ void detect_fmt_k(const int* __restrict__ ei) {
    if (blockIdx.x == 0 && threadIdx.x == 0) {
        int nz = 0;
        for (int i = 1; i < 2048; i += 2) nz += (ei[i] != 0);
        g_fmt = (nz == 0) ? 1 : 0;
    }
}
__global__ void zero_deg_k() {
    int i = blockIdx.x * blockDim.x + threadIdx.x;
    if (i < NN) g_deg[i] = 0;
}
__global__ void build_edges_k(const int* __restrict__ ei) {
    int e = blockIdx.x * blockDim.x + threadIdx.x;
    if (e >= ETOT) return;
    int s, d;
    if (e < E0) {
        if (g_fmt) { s = ei[2 * e]; d = ei[2 * E0 + 2 * e]; }
        else       { s = ei[e];     d = ei[E0 + e]; }
    } else {
        s = d = e - E0;
    }
    g_src32[e] = s;
    g_dst32[e] = d;
    atomicAdd(&g_deg[d], 1);
}
__global__ void scan_k() {
    __shared__ int vals[10240];
    __shared__ int sh[1024];
    const int t = threadIdx.x;
    const int CH = 10;
    #pragma unroll
    for (int i = 0; i < CH; i++) {
        int idx = t + i * 1024;
        vals[idx] = (idx < NN) ? g_deg[idx] : 0;
    }
    __syncthreads();
    int base = t * CH;
    int local = 0;
    #pragma unroll
    for (int i = 0; i < CH; i++) local += vals[base + i];
    sh[t] = local; __syncthreads();
    for (int o = 1; o < 1024; o <<= 1) {
        int v = (t >= o) ? sh[t - o] : 0;
        __syncthreads();
        sh[t] += v;
        __syncthreads();
    }
    int prefix = (t == 0) ? 0 : sh[t - 1];
    #pragma unroll
    for (int i = 0; i < CH; i++) {
        int idx = base + i;
        if (idx < NN) { g_off[idx] = prefix; g_cur[idx] = prefix; prefix += vals[idx]; }
    }
    if (t == 1023) g_off[NN] = sh[1023];
}
__global__ void fill_csr_k() {
    int e = blockIdx.x * blockDim.x + threadIdx.x;
    if (e < ETOT) {
        int d = g_dst32[e];
        int p = atomicAdd(&g_cur[d], 1);
        g_csr_eid[p] = e;
    }
}

// ---------------- conversions ----------------
__global__ void conv_act_k(const float* __restrict__ in, __nv_bfloat16* __restrict__ oh,
                           __nv_bfloat16* __restrict__ ol,
                           float* __restrict__ zs, float* __restrict__ zd,
                           int K, int Kpad, int M) {
    int idx = blockIdx.x * blockDim.x + threadIdx.x;
    if (idx < NN * HMAX) { zs[idx] = 0.f; zd[idx] = 0.f; }
    if (idx >= M * Kpad) return;
    int n = idx / Kpad, k = idx - n * Kpad;
    float v = (k < K) ? in[(size_t)n * K + k] : 0.f;
    __nv_bfloat16 h = __float2bfloat16(v);
    float r = v - __bfloat162float(h);
    oh[idx] = h;
    ol[idx] = __float2bfloat16(r);
}

__global__ void zero_pad_k(__nv_bfloat16* __restrict__ oh, __nv_bfloat16* __restrict__ ol) {
    int idx = blockIdx.x * blockDim.x + threadIdx.x;
    int n = idx / (KPAD2 - HC1), k = idx - n * (KPAD2 - HC1);
    if (n < NN) {
        oh[(size_t)n * KPAD2 + HC1 + k] = __float2bfloat16(0.f);
        ol[(size_t)n * KPAD2 + HC1 + k] = __float2bfloat16(0.f);
    }
}

__global__ void conv_w_k(const float* __restrict__ W, __nv_bfloat16* __restrict__ oh,
                         __nv_bfloat16* __restrict__ ol, int K, int N, int Kpad) {
    __shared__ float tile[32][33];
    int k0 = blockIdx.y * 32, n0 = blockIdx.x * 32;
    int tx = threadIdx.x, ty = threadIdx.y;
    #pragma unroll
    for (int i = 0; i < 4; i++) {
        int k = k0 + ty + 8 * i, n = n0 + tx;
        tile[ty + 8 * i][tx] = (k < K && n < N) ? W[(size_t)k * N + n] : 0.f;
    }
    __syncthreads();
    #pragma unroll
    for (int i = 0; i < 4; i++) {
        int n = n0 + ty + 8 * i, k = k0 + tx;
        if (n < N && k < Kpad) {
            float v = tile[tx][ty + 8 * i];
            __nv_bfloat16 h = __float2bfloat16(v);
            float r = v - __bfloat162float(h);
            oh[(size_t)n * Kpad + k] = h;
            ol[(size_t)n * Kpad + k] = __float2bfloat16(r);
        }
    }
}

// ============ bf16x3 GEMM (best config): SW64, 3-stage, 1 barrier/k-block, acc-major ============
#define TILEB   (128 * 64)
#define STAGEB  (4 * TILEB)
#define NSTAGE  3
#define GSMEM   (NSTAGE * STAGEB)     // 98304 per CTA -> 2 CTAs/SM

__device__ __forceinline__ void load_stage_mma(
    uint32_t sb, int s, int kOff, int tid, int m0, int n0, int M, int Nv, int Kpad,
    const __nv_bfloat16* __restrict__ Ah, const __nv_bfloat16* __restrict__ Al,
    const __nv_bfloat16* __restrict__ Bh, const __nv_bfloat16* __restrict__ Bl)
{
    uint32_t base = sb + s * STAGEB;
    #pragma unroll
    for (int i = 0; i < 8; i++) {
        int cid = tid + i * 256;
        int tile = cid >> 9;
        int idx = cid & 511;
        int r = idx >> 2, c = idx & 3;
        uint32_t sw = (uint32_t)((c ^ ((r >> 1) & 3)) << 4);
        uint32_t dst = base + tile * TILEB + (r << 6) + sw;
        const __nv_bfloat16* p;
        int row, lim;
        if (tile < 2) { p = (tile == 0) ? Ah : Al; row = m0 + r; lim = M; }
        else          { p = (tile == 2) ? Bh : Bl; row = n0 + r; lim = Nv; }
        int valid = row < lim;
        const __nv_bfloat16* src = p + (size_t)(valid ? row : 0) * Kpad + kOff + c * 8;
        cp_async16(dst, src, valid ? 16 : 0);
    }
    asm volatile("cp.async.commit_group;" ::: "memory");
}

__global__ __launch_bounds__(256, 2)
void gemm_mma_k(const __nv_bfloat16* __restrict__ Ah, const __nv_bfloat16* __restrict__ Al,
                const __nv_bfloat16* __restrict__ Bh, const __nv_bfloat16* __restrict__ Bl,
                float* __restrict__ C, int M, int Nv, int Kpad, int kStart, int KB,
                const float* __restrict__ attS, const float* __restrict__ attD,
                float* __restrict__ asrc, float* __restrict__ adst, int H)
{
    extern __shared__ char smem[];
    uint32_t sb = smem_u32(smem);
    const int tid  = threadIdx.x;
    const int lane = tid & 31;
    const int wid  = tid >> 5;
    const int wm = wid & 3;
    const int wn = wid >> 2;
    const int m0 = blockIdx.y * 128, n0 = blockIdx.x * 128;

    float acc[2][8][4];
    #pragma unroll
    for (int i = 0; i < 2; i++)
        #pragma unroll
        for (int j = 0; j < 8; j++)
            #pragma unroll
            for (int q = 0; q < 4; q++) acc[i][j][q] = 0.f;

    const int a_row0 = wm * 32 + (lane & 15);
    const int a_cb   = (lane >> 4);
    const int b_row0 = wn * 64 + ((lane >> 4) << 3) + (lane & 7);
    const int b_cb   = ((lane >> 3) & 1);
    const int xa = (a_row0 >> 1) & 3;
    const int xb = (b_row0 >> 1) & 3;

    load_stage_mma(sb, 0, kStart, tid, m0, n0, M, Nv, Kpad, Ah, Al, Bh, Bl);
    if (KB > 1)
        load_stage_mma(sb, 1, kStart + 32, tid, m0, n0, M, Nv, Kpad, Ah, Al, Bh, Bl);

    int sLoad = 2, sComp = 0;
    for (int kb = 0; kb < KB; kb++) {
        if (kb + 1 < KB) { asm volatile("cp.async.wait_group 1;" ::: "memory"); }
        else             { asm volatile("cp.async.wait_group 0;" ::: "memory"); }
        __syncthreads();
        if (kb + 2 < KB) {
            load_stage_mma(sb, sLoad, kStart + (kb + 2) * 32, tid, m0, n0, M, Nv, Kpad,
                           Ah, Al, Bh, Bl);
            sLoad = (sLoad + 1 == NSTAGE) ? 0 : sLoad + 1;
        }

        uint32_t base = sb + sComp * STAGEB;
        sComp = (sComp + 1 == NSTAGE) ? 0 : sComp + 1;
        uint32_t ah_b = base;
        uint32_t al_b = base + TILEB;
        uint32_t bh_b = base + 2 * TILEB;
        uint32_t bl_b = base + 3 * TILEB;

        #pragma unroll
        for (int kk = 0; kk < 2; kk++) {
            uint32_t ah[2][4], al[2][4];
            const uint32_t swA = (uint32_t)((((kk << 1) + a_cb) ^ xa) << 4);
            #pragma unroll
            for (int mf = 0; mf < 2; mf++) {
                int rowA = a_row0 + mf * 16;
                uint32_t addr = ah_b + (rowA << 6) + swA;
                ldsm_x4(ah[mf][0], ah[mf][1], ah[mf][2], ah[mf][3], addr);
                addr = al_b + (rowA << 6) + swA;
                ldsm_x4(al[mf][0], al[mf][1], al[mf][2], al[mf][3], addr);
            }
            const uint32_t swB = (uint32_t)((((kk << 1) + b_cb) ^ xb) << 4);
            #pragma unroll
            for (int hh = 0; hh < 2; hh++) {
                uint32_t bh[4][2], bl[4][2];
                #pragma unroll
                for (int p = 0; p < 2; p++) {
                    int rowB = b_row0 + (hh * 2 + p) * 16;
                    uint32_t addr = bh_b + (rowB << 6) + swB;
                    ldsm_x4(bh[2*p][0], bh[2*p][1], bh[2*p+1][0], bh[2*p+1][1], addr);
                    addr = bl_b + (rowB << 6) + swB;
                    ldsm_x4(bl[2*p][0], bl[2*p][1], bl[2*p+1][0], bl[2*p+1][1], addr);
                }
                #pragma unroll
                for (int mf = 0; mf < 2; mf++)
                    #pragma unroll
                    for (int j = 0; j < 4; j++) {
                        int nf = hh * 4 + j;
                        mma_bf16(acc[mf][nf], ah[mf], bh[j]);
                        mma_bf16(acc[mf][nf], ah[mf], bl[j]);
                        mma_bf16(acc[mf][nf], al[mf], bh[j]);
                    }
            }
        }
    }

    // ---- store C ----
    #pragma unroll
    for (int mf = 0; mf < 2; mf++) {
        int row = m0 + wm * 32 + mf * 16 + (lane >> 2);
        #pragma unroll
        for (int nf = 0; nf < 8; nf++) {
            int col = n0 + wn * 64 + nf * 8 + (lane & 3) * 2;
            if (col < Nv) {
                if (row < M)
                    *(float2*)(C + (size_t)row * Nv + col) = make_float2(acc[mf][nf][0], acc[mf][nf][1]);
                if (row + 8 < M)
                    *(float2*)(C + (size_t)(row + 8) * Nv + col) = make_float2(acc[mf][nf][2], acc[mf][nf][3]);
            }
        }
    }

    // ---- fused attention-dot partials ----
    if (attS) {
        const int w0 = n0 + wn * 64;
        const int headA = w0 / HID;
        const int colB  = (headA + 1) * HID;
        const bool twoSeg = (colB < w0 + 64) && (colB < Nv);
        #pragma unroll
        for (int mf = 0; mf < 2; mf++) {
            #pragma unroll
            for (int rp = 0; rp < 2; rp++) {
                int row = m0 + wm * 32 + mf * 16 + (lane >> 2) + rp * 8;
                float s0 = 0.f, s1 = 0.f, d0 = 0.f, d1 = 0.f;
                #pragma unroll
                for (int nf = 0; nf < 8; nf++) {
                    #pragma unroll
                    for (int q = 0; q < 2; q++) {
                        int col = w0 + nf * 8 + (lane & 3) * 2 + q;
                        float av = acc[mf][nf][rp * 2 + q];
                        float vs = 0.f, vd = 0.f;
                        if (col < Nv) { vs = attS[col]; vd = attD[col]; }
                        if (col < colB) { s0 += av * vs; d0 += av * vd; }
                        else            { s1 += av * vs; d1 += av * vd; }
                    }
                }
                #pragma unroll
                for (int o = 1; o < 4; o <<= 1) {
                    s0 += __shfl_xor_sync(0xffffffffu, s0, o);
                    s1 += __shfl_xor_sync(0xffffffffu, s1, o);
                    d0 += __shfl_xor_sync(0xffffffffu, d0, o);
                    d1 += __shfl_xor_sync(0xffffffffu, d1, o);
                }
                if ((lane & 3) == 0 && row < M) {
                    atomicAdd(&asrc[row * H + headA], s0);
                    atomicAdd(&adst[row * H + headA], d0);
                    if (twoSeg) {
                        atomicAdd(&asrc[row * H + headA + 1], s1);
                        atomicAdd(&adst[row * H + headA + 1], d1);
                    }
                }
            }
        }
    }
}

// ---------------- fused split-K sum + layer-3 attention dots ----------------
__global__ void add4_dots_k(const float* __restrict__ p0, const float* __restrict__ p1,
                            const float* __restrict__ p2, const float* __restrict__ p3,
                            float* __restrict__ h,
                            const float* __restrict__ as3, const float* __restrict__ ad3,
                            float* __restrict__ asrc, float* __restrict__ adst) {
    __shared__ float sh_s[HC3], sh_d[HC3];
    int n = blockIdx.x;
    int c = threadIdx.x;
    if (c < HC3) {
        size_t i = (size_t)n * HC3 + c;
        float v = (p0[i] + p1[i]) + (p2[i] + p3[i]);
        h[i] = v;
        sh_s[c] = v * as3[c];
        sh_d[c] = v * ad3[c];
    }
    __syncthreads();
    if (c < H3) {
        float ss = 0.f, dd = 0.f;
        #pragma unroll
        for (int q = 0; q < NCLS; q++) {
            ss += sh_s[c * NCLS + q];
            dd += sh_d[c * NCLS + q];
        }
        asrc[n * H3 + c] = ss;
        adst[n * H3 + c] = dd;
    }
}

// ---------------- segment softmax: pass1 caches leaky logits in alpha ----------------
__global__ void edge_softmax_k(const float* __restrict__ asrc,
                               const float* __restrict__ adst,
                               float* __restrict__ alpha,
                               float* __restrict__ invs, int H) {
    int idx = blockIdx.x * blockDim.x + threadIdx.x;
    if (idx >= NN * H) return;
    int n = idx / H, head = idx - n * H;
    int beg = g_off[n], end = g_off[n + 1];
    float ad = adst[idx];
    float m = -1e30f;
    for (int j = beg; j < end; j++) {
        int e = g_csr_eid[j];
        float v = asrc[g_src32[e] * H + head] + ad;
        v = v > 0.f ? v : 0.2f * v;
        alpha[(size_t)e * H + head] = v;      // cache logit (single random gather)
        m = fmaxf(m, v);
    }
    float s = 0.f;
    for (int j = beg; j < end; j++) {
        int e = g_csr_eid[j];
        float ex = __expf(alpha[(size_t)e * H + head] - m);
        alpha[(size_t)e * H + head] = ex;
        s += ex;
    }
    invs[idx] = 1.f / (s + 1e-16f);
}

// ---------------- aggregation ----------------
__global__ void aggregate_k(const float* __restrict__ h,
                            const float* __restrict__ alpha,
                            const float* __restrict__ invs,
                            const float* __restrict__ skip,
                            const float* __restrict__ bias,
                            float* __restrict__ out,             // may be null
                            __nv_bfloat16* __restrict__ oh,
                            __nv_bfloat16* __restrict__ ol,
                            float* __restrict__ zs,              // may be null
                            float* __restrict__ zd,
                            int H, int C) {
    const int HC = H * C;
    int n = blockIdx.y;
    if (zs && blockIdx.x == 0 && threadIdx.x < HMAX) {
        zs[n * HMAX + threadIdx.x] = 0.f;
        zd[n * HMAX + threadIdx.x] = 0.f;
    }
    int f = (blockIdx.x * blockDim.x + threadIdx.x) * 4;
    if (f >= HC) return;
    int head = f / C;
    int beg = g_off[n], end = g_off[n + 1];
    float4 acc = make_float4(0.f, 0.f, 0.f, 0.f);
    for (int j = beg; j < end; j++) {
        int e = g_csr_eid[j];
        float a = alpha[(size_t)e * H + head];
        float4 hv = *(const float4*)(h + (size_t)g_src32[e] * HC + f);
        acc.x += a * hv.x; acc.y += a * hv.y; acc.z += a * hv.z; acc.w += a * hv.w;
    }
    float inv = invs[n * H + head];
    acc.x *= inv; acc.y *= inv; acc.z *= inv; acc.w *= inv;
    float4 b4 = *(const float4*)(bias + f);
    acc.x += b4.x; acc.y += b4.y; acc.z += b4.z; acc.w += b4.w;
    if (skip) {
        float4 s4 = *(const float4*)(skip + (size_t)n * HC + f);
        acc.x += s4.x; acc.y += s4.y; acc.z += s4.z; acc.w += s4.w;
    }
    acc.x = acc.x > 0.f ? acc.x : expm1f(acc.x);
    acc.y = acc.y > 0.f ? acc.y : expm1f(acc.y);
    acc.z = acc.z > 0.f ? acc.z : expm1f(acc.z);
    acc.w = acc.w > 0.f ? acc.w : expm1f(acc.w);
    if (out) *(float4*)(out + (size_t)n * HC + f) = acc;
    float v[4] = {acc.x, acc.y, acc.z, acc.w};
    __nv_bfloat16 hh[4], ll[4];
    #pragma unroll
    for (int q = 0; q < 4; q++) {
        hh[q] = __float2bfloat16(v[q]);
        ll[q] = __float2bfloat16(v[q] - __bfloat162float(hh[q]));
    }
    *(uint2*)(oh + (size_t)n * KPAD2 + f) = *(uint2*)hh;
    *(uint2*)(ol + (size_t)n * KPAD2 + f) = *(uint2*)ll;
}

__global__ void aggregate3_k(const float* __restrict__ h,
                             const float* __restrict__ alpha,
                             const float* __restrict__ invs,
                             const float* __restrict__ bias,
                             float* __restrict__ out3) {
    int n = blockIdx.x;
    int c = threadIdx.x;
    if (c >= NCLS) return;
    int beg = g_off[n], end = g_off[n + 1];
    float acc = 0.f;
    #pragma unroll
    for (int head = 0; head < H3; head++) {
        float a2 = 0.f;
        for (int j = beg; j < end; j++) {
            int e = g_csr_eid[j];
            a2 += alpha[(size_t)e * H3 + head] *
                  h[(size_t)g_src32[e] * HC3 + head * NCLS + c];
        }
        acc += a2 * invs[n * H3 + head];
    }
    out3[n * NCLS + c] = acc * (1.f / H3) + bias[c];
}

__global__ void colsum_k(const float* __restrict__ out3, float* __restrict__ pooled) {
    int c = blockIdx.x;
    float s = 0.f;
    for (int n = threadIdx.x; n < NN; n += blockDim.x) s += out3[n * NCLS + c];
    __shared__ float sh[256];
    sh[threadIdx.x] = s; __syncthreads();
    for (int o = 128; o > 0; o >>= 1) {
        if (threadIdx.x < o) sh[threadIdx.x] += sh[threadIdx.x + o];
        __syncthreads();
    }
    if (threadIdx.x == 0) pooled[c] = sh[0];
}

__global__ void finalize_k(const float* __restrict__ pooled, float* __restrict__ out) {
    if (threadIdx.x == 0 && blockIdx.x == 0) {
        float m = -1e30f;
        for (int i = 0; i < NCLS; i++) m = fmaxf(m, pooled[i]);
        float s = 0.f;
        for (int i = 0; i < NCLS; i++) s += expf(pooled[i] - m);
        float lse = logf(s) + m;
        for (int i = 0; i < NCLS; i++) {
            out[i]        = pooled[i];
            out[NCLS + i] = pooled[i] - lse;
        }
    }
}

// ---------------- host resources (lazy init) ----------------
static bool        s_init = false;
static cudaStream_t s_s2, s_s3, s_s4;
static cudaEvent_t  s_e0, s_eGraph, s_eW1, s_eW2, s_eW3, s_eG1, s_ePad, s_eAgg2,
                    s_e3b, s_e3c, s_e3d;

extern "C" void kernel_launch(void* const* d_in, const int* in_sizes, int n_in,
                              void* d_out, int out_size) {
    const float* x   = (const float*)d_in[0];
    const int*   ei  = (const int*)  d_in[1];
    const float* W1  = (const float*)d_in[2];
    const float* as1 = (const float*)d_in[3];
    const float* ad1 = (const float*)d_in[4];
    const float* b1  = (const float*)d_in[5];
    const float* W2  = (const float*)d_in[6];
    const float* as2 = (const float*)d_in[7];
    const float* ad2 = (const float*)d_in[8];
    const float* b2  = (const float*)d_in[9];
    const float* W3  = (const float*)d_in[10];
    const float* as3 = (const float*)d_in[11];
    const float* ad3 = (const float*)d_in[12];
    const float* b3  = (const float*)d_in[13];
    float* out = (float*)d_out;

    float *bufA, *bufB, *alpha, *asrc, *adst, *invs, *out3, *pooled;
    __nv_bfloat16 *Ah, *Al, *B1h, *B1l, *B2h, *B2l, *B3h, *B3l;
    cudaGetSymbolAddress((void**)&bufA,   g_bufA);
    cudaGetSymbolAddress((void**)&bufB,   g_bufB);
    cudaGetSymbolAddress((void**)&alpha,  g_alpha);
    cudaGetSymbolAddress((void**)&asrc,   g_asrc);
    cudaGetSymbolAddress((void**)&adst,   g_adst);
    cudaGetSymbolAddress((void**)&invs,   g_invs);
    cudaGetSymbolAddress((void**)&out3,   g_out3);
    cudaGetSymbolAddress((void**)&pooled, g_pooled);
    cudaGetSymbolAddress((void**)&Ah,  g_Ah);
    cudaGetSymbolAddress((void**)&Al,  g_Al);
    cudaGetSymbolAddress((void**)&B1h, g_B1h);
    cudaGetSymbolAddress((void**)&B1l, g_B1l);
    cudaGetSymbolAddress((void**)&B2h, g_B2h);
    cudaGetSymbolAddress((void**)&B2l, g_B2l);
    cudaGetSymbolAddress((void**)&B3h, g_B3h);
    cudaGetSymbolAddress((void**)&B3l, g_B3l);

    if (!s_init) {
        cudaFuncSetAttribute(gemm_mma_k, cudaFuncAttributeMaxDynamicSharedMemorySize, GSMEM);
        cudaStreamCreateWithFlags(&s_s2, cudaStreamNonBlocking);
        cudaStreamCreateWithFlags(&s_s3, cudaStreamNonBlocking);
        cudaStreamCreateWithFlags(&s_s4, cudaStreamNonBlocking);
        cudaEventCreateWithFlags(&s_e0,     cudaEventDisableTiming);
        cudaEventCreateWithFlags(&s_eGraph, cudaEventDisableTiming);
        cudaEventCreateWithFlags(&s_eW1,    cudaEventDisableTiming);
        cudaEventCreateWithFlags(&s_eW2,    cudaEventDisableTiming);
        cudaEventCreateWithFlags(&s_eW3,    cudaEventDisableTiming);
        cudaEventCreateWithFlags(&s_eG1,    cudaEventDisableTiming);
        cudaEventCreateWithFlags(&s_ePad,   cudaEventDisableTiming);
        cudaEventCreateWithFlags(&s_eAgg2,  cudaEventDisableTiming);
        cudaEventCreateWithFlags(&s_e3b,    cudaEventDisableTiming);
        cudaEventCreateWithFlags(&s_e3c,    cudaEventDisableTiming);
        cudaEventCreateWithFlags(&s_e3d,    cudaEventDisableTiming);
        s_init = true;
    }
    cudaStream_t s2 = s_s2, s3 = s_s3, s4 = s_s4;

    const dim3 gemm_grid12((HC1 + 127) / 128, (NN + 127) / 128);   // 12 x 79
    const dim3 gemm_grid3 (1, (NN + 127) / 128);
    const int sm_blocks1 = (NN * H1 + 255) / 256;
    const int sm_blocks3 = (NN * H3 + 255) / 256;
    const dim3 agg_grid((HC1 / 4 + 127) / 128, NN);
    const dim3 convw_block(32, 8);

    cudaEventRecord(s_e0, 0);
    cudaStreamWaitEvent(s2, s_e0, 0);
    cudaStreamWaitEvent(s3, s_e0, 0);
    cudaStreamWaitEvent(s4, s_e0, 0);

    // keep the layer-1 GEMM as the 4th submitted launch for ncu
    {
        dim3 cwg1((HC1 + 31) / 32, (FIN + 31) / 32);
        conv_w_k<<<cwg1, convw_block, 0, s3>>>(W1, B1h, B1l, FIN, HC1, FIN);      // #1
        cudaEventRecord(s_eW1, s3);
    }
    conv_act_k<<<(NN * FIN + 255) / 256, 256>>>(x, Ah, Al, asrc, adst, FIN, FIN, NN); // #2
    {
        dim3 cwg2((HC1 + 31) / 32, (KPAD2 + 31) / 32);
        conv_w_k<<<cwg2, convw_block, 0, s3>>>(W2, B2h, B2l, HC1, HC1, KPAD2);    // #3
        cudaEventRecord(s_eW2, s3);
    }
    cudaStreamWaitEvent(0, s_eW1, 0);
    gemm_mma_k<<<gemm_grid12, 256, GSMEM>>>(Ah, Al, B1h, B1l, bufA, NN, HC1, FIN, // #4
                                            0, FIN / 32, as1, ad1, asrc, adst, H1);
    cudaEventRecord(s_eG1, 0);

    {
        dim3 cwg3((HC3 + 31) / 32, (KPAD2 + 31) / 32);
        conv_w_k<<<cwg3, convw_block, 0, s3>>>(W3, B3h, B3l, HC1, HC3, KPAD2);    // #5
        cudaEventRecord(s_eW3, s3);
    }

    // s2: graph build, concurrent with gemm1
    detect_fmt_k<<<1, 1, 0, s2>>>(ei);
    zero_deg_k<<<(NN + 255) / 256, 256, 0, s2>>>();
    build_edges_k<<<(ETOT + 255) / 256, 256, 0, s2>>>(ei);
    scan_k<<<1, 1024, 0, s2>>>();
    fill_csr_k<<<(ETOT + 255) / 256, 256, 0, s2>>>();
    cudaEventRecord(s_eGraph, s2);

    cudaStreamWaitEvent(s3, s_eG1, 0);
    zero_pad_k<<<(NN * (KPAD2 - HC1) + 255) / 256, 256, 0, s3>>>(Ah, Al);
    cudaEventRecord(s_ePad, s3);

    // layer 1
    cudaStreamWaitEvent(0, s_eGraph, 0);
    edge_softmax_k<<<sm_blocks1, 256>>>(asrc, adst, alpha, invs, H1);
    aggregate_k<<<agg_grid, 128>>>(bufA, alpha, invs, nullptr, b1, bufB, Ah, Al,
                                   asrc, adst, H1, HID);

    // layer 2
    cudaStreamWaitEvent(0, s_eW2, 0);
    cudaStreamWaitEvent(0, s_ePad, 0);
    gemm_mma_k<<<gemm_grid12, 256, GSMEM>>>(Ah, Al, B2h, B2l, bufA, NN, HC1, KPAD2,
                                            0, KPAD2 / 32, as2, ad2, asrc, adst, H1);
    edge_softmax_k<<<sm_blocks1, 256>>>(asrc, adst, alpha, invs, H1);
    aggregate_k<<<agg_grid, 128>>>(bufA, alpha, invs, bufB, b2, nullptr, Ah, Al,
                                   nullptr, nullptr, H1, HID);
    cudaEventRecord(s_eAgg2, 0);

    // layer 3: split-K x4
    float* part0 = bufB;
    float* part1 = bufB + 1 * (size_t)NN * HC3;
    float* part2 = bufB + 2 * (size_t)NN * HC3;
    float* part3 = bufB + 3 * (size_t)NN * HC3;
    const int KQ = KPAD2 / 4;
    cudaStreamWaitEvent(s2, s_eAgg2, 0);
    cudaStreamWaitEvent(s3, s_eAgg2, 0);
    cudaStreamWaitEvent(s4, s_eAgg2, 0);
    cudaStreamWaitEvent(s2, s_eW3, 0);
    cudaStreamWaitEvent(s3, s_eW3, 0);
    cudaStreamWaitEvent(s4, s_eW3, 0);
    cudaStreamWaitEvent(0,  s_eW3, 0);
    gemm_mma_k<<<gemm_grid3, 256, GSMEM, s2>>>(Ah, Al, B3h, B3l, part1, NN, HC3, KPAD2,
                                               1 * KQ, KQ / 32, nullptr, nullptr, nullptr, nullptr, 0);
    cudaEventRecord(s_e3b, s2);
    gemm_mma_k<<<gemm_grid3, 256, GSMEM, s3>>>(Ah, Al, B3h, B3l, part2, NN, HC3, KPAD2,
                                               2 * KQ, KQ / 32, nullptr, nullptr, nullptr, nullptr, 0);
    cudaEventRecord(s_e3c, s3);
    gemm_mma_k<<<gemm_grid3, 256, GSMEM, s4>>>(Ah, Al, B3h, B3l, part3, NN, HC3, KPAD2,
                                               3 * KQ, KQ / 32, nullptr, nullptr, nullptr, nullptr, 0);
    cudaEventRecord(s_e3d, s4);
    gemm_mma_k<<<gemm_grid3, 256, GSMEM>>>(Ah, Al, B3h, B3l, part0, NN, HC3, KPAD2,
                                           0, KQ / 32, nullptr, nullptr, nullptr, nullptr, 0);
    cudaStreamWaitEvent(0, s_e3b, 0);
    cudaStreamWaitEvent(0, s_e3c, 0);
    cudaStreamWaitEvent(0, s_e3d, 0);
    add4_dots_k<<<NN, 128>>>(part0, part1, part2, part3, bufA, as3, ad3, asrc, adst);

    edge_softmax_k<<<sm_blocks3, 256>>>(asrc, adst, alpha, invs, H3);
    aggregate3_k<<<NN, 64>>>(bufA, alpha, invs, b3, out3);

    colsum_k<<<NCLS, 256>>>(out3, pooled);
    finalize_k<<<1, 32>>>(pooled, out);
}

// round 16
// speedup vs baseline: 1.0408x; 1.0408x over previous
#include <cuda_runtime.h>
#include <cuda_bf16.h>
#include <math.h>
#include <cstdint>

// ---------------- problem constants ----------------
#define NN      10000
#define E0      80000
#define ETOT    (E0 + NN)
#define FIN     128
#define HID     300
#define H1      5
#define HC1     (H1*HID)       // 1500
#define H3      3
#define NCLS    40
#define HC3     (H3*NCLS)      // 120
#define HMAX    5
#define KPAD2   1536

// ---------------- static device scratch ----------------
__device__ __align__(16) float g_bufA[(size_t)NN * HC1];
__device__ __align__(16) float g_bufB[(size_t)NN * HC1];
__device__ __align__(16) float g_alpha[(size_t)ETOT * HMAX];
__device__ __align__(16) float g_asrc[NN * HMAX];
__device__ __align__(16) float g_adst[NN * HMAX];
__device__ __align__(16) float g_invs[NN * HMAX];
__device__ __align__(16) float g_out3[NN * NCLS];
__device__ float g_pooled[NCLS];
__device__ int   g_deg[NN];
__device__ int   g_off[NN + 1];
__device__ int   g_cur[NN];
__device__ int   g_src_sorted[ETOT];   // CSR-ordered source node ids
__device__ int   g_src32[ETOT];
__device__ int   g_dst32[ETOT];
__device__ int   g_fmt;

__device__ __align__(16) __nv_bfloat16 g_Ah[(size_t)NN * KPAD2];
__device__ __align__(16) __nv_bfloat16 g_Al[(size_t)NN * KPAD2];
__device__ __align__(16) __nv_bfloat16 g_B1h[(size_t)HC1 * FIN];
__device__ __align__(16) __nv_bfloat16 g_B1l[(size_t)HC1 * FIN];
__device__ __align__(16) __nv_bfloat16 g_B2h[(size_t)HC1 * KPAD2];
__device__ __align__(16) __nv_bfloat16 g_B2l[(size_t)HC1 * KPAD2];
__device__ __align__(16) __nv_bfloat16 g_B3h[(size_t)HC3 * KPAD2];
__device__ __align__(16) __nv_bfloat16 g_B3l[(size_t)HC3 * KPAD2];

// ================= helpers =================
__device__ __forceinline__ uint32_t smem_u32(const void* p) {
    uint32_t a;
    asm("{ .reg .u64 t; cvta.to.shared.u64 t, %1; cvt.u32.u64 %0, t; }" : "=r"(a) : "l"(p));
    return a;
}
__device__ __forceinline__ void cp_async16(uint32_t dst, const void* src, int src_bytes) {
    asm volatile("cp.async.cg.shared.global [%0], [%1], 16, %2;"
                 :: "r"(dst), "l"(src), "r"(src_bytes) : "memory");
}
__device__ __forceinline__ void ldsm_x4(uint32_t& r0, uint32_t& r1, uint32_t& r2, uint32_t& r3,
                                        uint32_t addr) {
    asm volatile("ldmatrix.sync.aligned.m8n8.x4.shared.b16 {%0,%1,%2,%3}, [%4];"
                 : "=r"(r0), "=r"(r1), "=r"(r2), "=r"(r3) : "r"(addr));
}
__device__ __forceinline__ void mma_bf16(float* c, const uint32_t* a, const uint32_t* b) {
    asm volatile("mma.sync.aligned.m16n8k16.row.col.f32.bf16.bf16.f32 "
                 "{%0,%1,%2,%3}, {%4,%5,%6,%7}, {%8,%9}, {%0,%1,%2,%3};"
                 : "+f"(c[0]), "+f"(c[1]), "+f"(c[2]), "+f"(c[3])
                 : "r"(a[0]), "r"(a[1]), "r"(a[2]), "r"(a[3]), "r"(b[0]), "r"(b[1]));
}

// ---------------- graph construction ----------------
__global__ void detect_fmt_k(const int* __restrict__ ei) {
    if (blockIdx.x == 0 && threadIdx.x == 0) {
        int nz = 0;
        for (int i = 1; i < 2048; i += 2) nz += (ei[i] != 0);
        g_fmt = (nz == 0) ? 1 : 0;
    }
}
__global__ void zero_deg_k() {
    int i = blockIdx.x * blockDim.x + threadIdx.x;
    if (i < NN) g_deg[i] = 0;
}
__global__ void build_edges_k(const int* __restrict__ ei) {
    int e = blockIdx.x * blockDim.x + threadIdx.x;
    if (e >= ETOT) return;
    int s, d;
    if (e < E0) {
        if (g_fmt) { s = ei[2 * e]; d = ei[2 * E0 + 2 * e]; }
        else       { s = ei[e];     d = ei[E0 + e]; }
    } else {
        s = d = e - E0;
    }
    g_src32[e] = s;
    g_dst32[e] = d;
    atomicAdd(&g_deg[d], 1);
}
__global__ void scan_k() {
    __shared__ int vals[10240];
    __shared__ int sh[1024];
    const int t = threadIdx.x;
    const int CH = 10;
    #pragma unroll
    for (int i = 0; i < CH; i++) {
        int idx = t + i * 1024;
        vals[idx] = (idx < NN) ? g_deg[idx] : 0;
    }
    __syncthreads();
    int base = t * CH;
    int local = 0;
    #pragma unroll
    for (int i = 0; i < CH; i++) local += vals[base + i];
    sh[t] = local; __syncthreads();
    for (int o = 1; o < 1024; o <<= 1) {
        int v = (t >= o) ? sh[t - o] : 0;
        __syncthreads();
        sh[t] += v;
        __syncthreads();
    }
    int prefix = (t == 0) ? 0 : sh[t - 1];
    #pragma unroll
    for (int i = 0; i < CH; i++) {
        int idx = base + i;
        if (idx < NN) { g_off[idx] = prefix; g_cur[idx] = prefix; prefix += vals[idx]; }
    }
    if (t == 1023) g_off[NN] = sh[1023];
}
// scatter edges into CSR slots; store the SOURCE id directly (kills eid indirection)
__global__ void fill_csr_k() {
    int e = blockIdx.x * blockDim.x + threadIdx.x;
    if (e < ETOT) {
        int d = g_dst32[e];
        int p = atomicAdd(&g_cur[d], 1);
        g_src_sorted[p] = g_src32[e];
    }
}

// ---------------- conversions ----------------
__global__ void conv_act_k(const float* __restrict__ in, __nv_bfloat16* __restrict__ oh,
                           __nv_bfloat16* __restrict__ ol,
                           float* __restrict__ zs, float* __restrict__ zd,
                           int K, int Kpad, int M) {
    int idx = blockIdx.x * blockDim.x + threadIdx.x;
    if (idx < NN * HMAX) { zs[idx] = 0.f; zd[idx] = 0.f; }
    if (idx >= M * Kpad) return;
    int n = idx / Kpad, k = idx - n * Kpad;
    float v = (k < K) ? in[(size_t)n * K + k] : 0.f;
    __nv_bfloat16 h = __float2bfloat16(v);
    float r = v - __bfloat162float(h);
    oh[idx] = h;
    ol[idx] = __float2bfloat16(r);
}

__global__ void zero_pad_k(__nv_bfloat16* __restrict__ oh, __nv_bfloat16* __restrict__ ol) {
    int idx = blockIdx.x * blockDim.x + threadIdx.x;
    int n = idx / (KPAD2 - HC1), k = idx - n * (KPAD2 - HC1);
    if (n < NN) {
        oh[(size_t)n * KPAD2 + HC1 + k] = __float2bfloat16(0.f);
        ol[(size_t)n * KPAD2 + HC1 + k] = __float2bfloat16(0.f);
    }
}

__global__ void conv_w_k(const float* __restrict__ W, __nv_bfloat16* __restrict__ oh,
                         __nv_bfloat16* __restrict__ ol, int K, int N, int Kpad) {
    __shared__ float tile[32][33];
    int k0 = blockIdx.y * 32, n0 = blockIdx.x * 32;
    int tx = threadIdx.x, ty = threadIdx.y;
    #pragma unroll
    for (int i = 0; i < 4; i++) {
        int k = k0 + ty + 8 * i, n = n0 + tx;
        tile[ty + 8 * i][tx] = (k < K && n < N) ? W[(size_t)k * N + n] : 0.f;
    }
    __syncthreads();
    #pragma unroll
    for (int i = 0; i < 4; i++) {
        int n = n0 + ty + 8 * i, k = k0 + tx;
        if (n < N && k < Kpad) {
            float v = tile[tx][ty + 8 * i];
            __nv_bfloat16 h = __float2bfloat16(v);
            float r = v - __bfloat162float(h);
            oh[(size_t)n * Kpad + k] = h;
            ol[(size_t)n * Kpad + k] = __float2bfloat16(r);
        }
    }
}

// ============ bf16x3 GEMM (best config): SW64, 3-stage, 1 barrier/k-block, acc-major ============
#define TILEB   (128 * 64)
#define STAGEB  (4 * TILEB)
#define NSTAGE  3
#define GSMEM   (NSTAGE * STAGEB)     // 98304 per CTA -> 2 CTAs/SM

__device__ __forceinline__ void load_stage_mma(
    uint32_t sb, int s, int kOff, int tid, int m0, int n0, int M, int Nv, int Kpad,
    const __nv_bfloat16* __restrict__ Ah, const __nv_bfloat16* __restrict__ Al,
    const __nv_bfloat16* __restrict__ Bh, const __nv_bfloat16* __restrict__ Bl)
{
    uint32_t base = sb + s * STAGEB;
    #pragma unroll
    for (int i = 0; i < 8; i++) {
        int cid = tid + i * 256;
        int tile = cid >> 9;
        int idx = cid & 511;
        int r = idx >> 2, c = idx & 3;
        uint32_t sw = (uint32_t)((c ^ ((r >> 1) & 3)) << 4);
        uint32_t dst = base + tile * TILEB + (r << 6) + sw;
        const __nv_bfloat16* p;
        int row, lim;
        if (tile < 2) { p = (tile == 0) ? Ah : Al; row = m0 + r; lim = M; }
        else          { p = (tile == 2) ? Bh : Bl; row = n0 + r; lim = Nv; }
        int valid = row < lim;
        const __nv_bfloat16* src = p + (size_t)(valid ? row : 0) * Kpad + kOff + c * 8;
        cp_async16(dst, src, valid ? 16 : 0);
    }
    asm volatile("cp.async.commit_group;" ::: "memory");
}

__global__ __launch_bounds__(256, 2)
void gemm_mma_k(const __nv_bfloat16* __restrict__ Ah, const __nv_bfloat16* __restrict__ Al,
                const __nv_bfloat16* __restrict__ Bh, const __nv_bfloat16* __restrict__ Bl,
                float* __restrict__ C, int M, int Nv, int Kpad, int kStart, int KB,
                const float* __restrict__ attS, const float* __restrict__ attD,
                float* __restrict__ asrc, float* __restrict__ adst, int H)
{
    extern __shared__ char smem[];
    uint32_t sb = smem_u32(smem);
    const int tid  = threadIdx.x;
    const int lane = tid & 31;
    const int wid  = tid >> 5;
    const int wm = wid & 3;
    const int wn = wid >> 2;
    const int m0 = blockIdx.y * 128, n0 = blockIdx.x * 128;

    float acc[2][8][4];
    #pragma unroll
    for (int i = 0; i < 2; i++)
        #pragma unroll
        for (int j = 0; j < 8; j++)
            #pragma unroll
            for (int q = 0; q < 4; q++) acc[i][j][q] = 0.f;

    const int a_row0 = wm * 32 + (lane & 15);
    const int a_cb   = (lane >> 4);
    const int b_row0 = wn * 64 + ((lane >> 4) << 3) + (lane & 7);
    const int b_cb   = ((lane >> 3) & 1);
    const int xa = (a_row0 >> 1) & 3;
    const int xb = (b_row0 >> 1) & 3;

    load_stage_mma(sb, 0, kStart, tid, m0, n0, M, Nv, Kpad, Ah, Al, Bh, Bl);
    if (KB > 1)
        load_stage_mma(sb, 1, kStart + 32, tid, m0, n0, M, Nv, Kpad, Ah, Al, Bh, Bl);

    int sLoad = 2, sComp = 0;
    for (int kb = 0; kb < KB; kb++) {
        if (kb + 1 < KB) { asm volatile("cp.async.wait_group 1;" ::: "memory"); }
        else             { asm volatile("cp.async.wait_group 0;" ::: "memory"); }
        __syncthreads();
        if (kb + 2 < KB) {
            load_stage_mma(sb, sLoad, kStart + (kb + 2) * 32, tid, m0, n0, M, Nv, Kpad,
                           Ah, Al, Bh, Bl);
            sLoad = (sLoad + 1 == NSTAGE) ? 0 : sLoad + 1;
        }

        uint32_t base = sb + sComp * STAGEB;
        sComp = (sComp + 1 == NSTAGE) ? 0 : sComp + 1;
        uint32_t ah_b = base;
        uint32_t al_b = base + TILEB;
        uint32_t bh_b = base + 2 * TILEB;
        uint32_t bl_b = base + 3 * TILEB;

        #pragma unroll
        for (int kk = 0; kk < 2; kk++) {
            uint32_t ah[2][4], al[2][4];
            const uint32_t swA = (uint32_t)((((kk << 1) + a_cb) ^ xa) << 4);
            #pragma unroll
            for (int mf = 0; mf < 2; mf++) {
                int rowA = a_row0 + mf * 16;
                uint32_t addr = ah_b + (rowA << 6) + swA;
                ldsm_x4(ah[mf][0], ah[mf][1], ah[mf][2], ah[mf][3], addr);
                addr = al_b + (rowA << 6) + swA;
                ldsm_x4(al[mf][0], al[mf][1], al[mf][2], al[mf][3], addr);
            }
            const uint32_t swB = (uint32_t)((((kk << 1) + b_cb) ^ xb) << 4);
            #pragma unroll
            for (int hh = 0; hh < 2; hh++) {
                uint32_t bh[4][2], bl[4][2];
                #pragma unroll
                for (int p = 0; p < 2; p++) {
                    int rowB = b_row0 + (hh * 2 + p) * 16;
                    uint32_t addr = bh_b + (rowB << 6) + swB;
                    ldsm_x4(bh[2*p][0], bh[2*p][1], bh[2*p+1][0], bh[2*p+1][1], addr);
                    addr = bl_b + (rowB << 6) + swB;
                    ldsm_x4(bl[2*p][0], bl[2*p][1], bl[2*p+1][0], bl[2*p+1][1], addr);
                }
                #pragma unroll
                for (int mf = 0; mf < 2; mf++)
                    #pragma unroll
                    for (int j = 0; j < 4; j++) {
                        int nf = hh * 4 + j;
                        mma_bf16(acc[mf][nf], ah[mf], bh[j]);
                        mma_bf16(acc[mf][nf], ah[mf], bl[j]);
                        mma_bf16(acc[mf][nf], al[mf], bh[j]);
                    }
            }
        }
    }

    // ---- store C ----
    #pragma unroll
    for (int mf = 0; mf < 2; mf++) {
        int row = m0 + wm * 32 + mf * 16 + (lane >> 2);
        #pragma unroll
        for (int nf = 0; nf < 8; nf++) {
            int col = n0 + wn * 64 + nf * 8 + (lane & 3) * 2;
            if (col < Nv) {
                if (row < M)
                    *(float2*)(C + (size_t)row * Nv + col) = make_float2(acc[mf][nf][0], acc[mf][nf][1]);
                if (row + 8 < M)
                    *(float2*)(C + (size_t)(row + 8) * Nv + col) = make_float2(acc[mf][nf][2], acc[mf][nf][3]);
            }
        }
    }

    // ---- fused attention-dot partials ----
    if (attS) {
        const int w0 = n0 + wn * 64;
        const int headA = w0 / HID;
        const int colB  = (headA + 1) * HID;
        const bool twoSeg = (colB < w0 + 64) && (colB < Nv);
        #pragma unroll
        for (int mf = 0; mf < 2; mf++) {
            #pragma unroll
            for (int rp = 0; rp < 2; rp++) {
                int row = m0 + wm * 32 + mf * 16 + (lane >> 2) + rp * 8;
                float s0 = 0.f, s1 = 0.f, d0 = 0.f, d1 = 0.f;
                #pragma unroll
                for (int nf = 0; nf < 8; nf++) {
                    #pragma unroll
                    for (int q = 0; q < 2; q++) {
                        int col = w0 + nf * 8 + (lane & 3) * 2 + q;
                        float av = acc[mf][nf][rp * 2 + q];
                        float vs = 0.f, vd = 0.f;
                        if (col < Nv) { vs = attS[col]; vd = attD[col]; }
                        if (col < colB) { s0 += av * vs; d0 += av * vd; }
                        else            { s1 += av * vs; d1 += av * vd; }
                    }
                }
                #pragma unroll
                for (int o = 1; o < 4; o <<= 1) {
                    s0 += __shfl_xor_sync(0xffffffffu, s0, o);
                    s1 += __shfl_xor_sync(0xffffffffu, s1, o);
                    d0 += __shfl_xor_sync(0xffffffffu, d0, o);
                    d1 += __shfl_xor_sync(0xffffffffu, d1, o);
                }
                if ((lane & 3) == 0 && row < M) {
                    atomicAdd(&asrc[row * H + headA], s0);
                    atomicAdd(&adst[row * H + headA], d0);
                    if (twoSeg) {
                        atomicAdd(&asrc[row * H + headA + 1], s1);
                        atomicAdd(&adst[row * H + headA + 1], d1);
                    }
                }
            }
        }
    }
}

// ---------------- fused split-K sum + layer-3 attention dots ----------------
__global__ void add4_dots_k(const float* __restrict__ p0, const float* __restrict__ p1,
                            const float* __restrict__ p2, const float* __restrict__ p3,
                            float* __restrict__ h,
                            const float* __restrict__ as3, const float* __restrict__ ad3,
                            float* __restrict__ asrc, float* __restrict__ adst) {
    __shared__ float sh_s[HC3], sh_d[HC3];
    int n = blockIdx.x;
    int c = threadIdx.x;
    if (c < HC3) {
        size_t i = (size_t)n * HC3 + c;
        float v = (p0[i] + p1[i]) + (p2[i] + p3[i]);
        h[i] = v;
        sh_s[c] = v * as3[c];
        sh_d[c] = v * ad3[c];
    }
    __syncthreads();
    if (c < H3) {
        float ss = 0.f, dd = 0.f;
        #pragma unroll
        for (int q = 0; q < NCLS; q++) {
            ss += sh_s[c * NCLS + q];
            dd += sh_d[c * NCLS + q];
        }
        asrc[n * H3 + c] = ss;
        adst[n * H3 + c] = dd;
    }
}

// ---------------- segment softmax (CSR-ordered alpha; R13 structure) ----------------
__global__ void edge_softmax_k(const float* __restrict__ asrc,
                               const float* __restrict__ adst,
                               float* __restrict__ alpha,
                               float* __restrict__ invs, int H) {
    int idx = blockIdx.x * blockDim.x + threadIdx.x;
    if (idx >= NN * H) return;
    int n = idx / H, head = idx - n * H;
    int beg = g_off[n], end = g_off[n + 1];
    float ad = adst[idx];
    float m = -1e30f;
    for (int j = beg; j < end; j++) {
        float v = asrc[g_src_sorted[j] * H + head] + ad;
        v = v > 0.f ? v : 0.2f * v;
        m = fmaxf(m, v);
    }
    float s = 0.f;
    for (int j = beg; j < end; j++) {
        float v = asrc[g_src_sorted[j] * H + head] + ad;
        v = v > 0.f ? v : 0.2f * v;
        float ex = __expf(v - m);
        alpha[(size_t)j * H + head] = ex;   // CSR slot: contiguous per node
        s += ex;
    }
    invs[idx] = 1.f / (s + 1e-16f);
}

// ---------------- aggregation ----------------
__global__ void aggregate_k(const float* __restrict__ h,
                            const float* __restrict__ alpha,
                            const float* __restrict__ invs,
                            const float* __restrict__ skip,
                            const float* __restrict__ bias,
                            float* __restrict__ out,             // may be null
                            __nv_bfloat16* __restrict__ oh,
                            __nv_bfloat16* __restrict__ ol,
                            float* __restrict__ zs,              // may be null
                            float* __restrict__ zd,
                            int H, int C) {
    const int HC = H * C;
    int n = blockIdx.y;
    if (zs && blockIdx.x == 0 && threadIdx.x < HMAX) {
        zs[n * HMAX + threadIdx.x] = 0.f;
        zd[n * HMAX + threadIdx.x] = 0.f;
    }
    int f = (blockIdx.x * blockDim.x + threadIdx.x) * 4;
    if (f >= HC) return;
    int head = f / C;
    int beg = g_off[n], end = g_off[n + 1];
    float4 acc = make_float4(0.f, 0.f, 0.f, 0.f);
    for (int j = beg; j < end; j++) {
        float a = alpha[(size_t)j * H + head];
        float4 hv = *(const float4*)(h + (size_t)g_src_sorted[j] * HC + f);
        acc.x += a * hv.x; acc.y += a * hv.y; acc.z += a * hv.z; acc.w += a * hv.w;
    }
    float inv = invs[n * H + head];
    acc.x *= inv; acc.y *= inv; acc.z *= inv; acc.w *= inv;
    float4 b4 = *(const float4*)(bias + f);
    acc.x += b4.x; acc.y += b4.y; acc.z += b4.z; acc.w += b4.w;
    if (skip) {
        float4 s4 = *(const float4*)(skip + (size_t)n * HC + f);
        acc.x += s4.x; acc.y += s4.y; acc.z += s4.z; acc.w += s4.w;
    }
    acc.x = acc.x > 0.f ? acc.x : expm1f(acc.x);
    acc.y = acc.y > 0.f ? acc.y : expm1f(acc.y);
    acc.z = acc.z > 0.f ? acc.z : expm1f(acc.z);
    acc.w = acc.w > 0.f ? acc.w : expm1f(acc.w);
    if (out) *(float4*)(out + (size_t)n * HC + f) = acc;
    float v[4] = {acc.x, acc.y, acc.z, acc.w};
    __nv_bfloat16 hh[4], ll[4];
    #pragma unroll
    for (int q = 0; q < 4; q++) {
        hh[q] = __float2bfloat16(v[q]);
        ll[q] = __float2bfloat16(v[q] - __bfloat162float(hh[q]));
    }
    *(uint2*)(oh + (size_t)n * KPAD2 + f) = *(uint2*)hh;
    *(uint2*)(ol + (size_t)n * KPAD2 + f) = *(uint2*)ll;
}

__global__ void aggregate3_k(const float* __restrict__ h,
                             const float* __restrict__ alpha,
                             const float* __restrict__ invs,
                             const float* __restrict__ bias,
                             float* __restrict__ out3) {
    int n = blockIdx.x;
    int c = threadIdx.x;
    if (c >= NCLS) return;
    int beg = g_off[n], end = g_off[n + 1];
    float acc = 0.f;
    #pragma unroll
    for (int head = 0; head < H3; head++) {
        float a2 = 0.f;
        for (int j = beg; j < end; j++) {
            a2 += alpha[(size_t)j * H3 + head] *
                  h[(size_t)g_src_sorted[j] * HC3 + head * NCLS + c];
        }
        acc += a2 * invs[n * H3 + head];
    }
    out3[n * NCLS + c] = acc * (1.f / H3) + bias[c];
}

__global__ void colsum_k(const float* __restrict__ out3, float* __restrict__ pooled) {
    int c = blockIdx.x;
    float s = 0.f;
    for (int n = threadIdx.x; n < NN; n += blockDim.x) s += out3[n * NCLS + c];
    __shared__ float sh[256];
    sh[threadIdx.x] = s; __syncthreads();
    for (int o = 128; o > 0; o >>= 1) {
        if (threadIdx.x < o) sh[threadIdx.x] += sh[threadIdx.x + o];
        __syncthreads();
    }
    if (threadIdx.x == 0) pooled[c] = sh[0];
}

__global__ void finalize_k(const float* __restrict__ pooled, float* __restrict__ out) {
    if (threadIdx.x == 0 && blockIdx.x == 0) {
        float m = -1e30f;
        for (int i = 0; i < NCLS; i++) m = fmaxf(m, pooled[i]);
        float s = 0.f;
        for (int i = 0; i < NCLS; i++) s += expf(pooled[i] - m);
        float lse = logf(s) + m;
        for (int i = 0; i < NCLS; i++) {
            out[i]        = pooled[i];
            out[NCLS + i] = pooled[i] - lse;
        }
    }
}

// ---------------- host resources (lazy init) ----------------
static bool        s_init = false;
static cudaStream_t s_s2, s_s3, s_s4;
static cudaEvent_t  s_e0, s_eGraph, s_eW1, s_eW2, s_eW3, s_eG1, s_ePad, s_eAgg2,
                    s_e3b, s_e3c, s_e3d;

extern "C" void kernel_launch(void* const* d_in, const int* in_sizes, int n_in,
                              void* d_out, int out_size) {
    const float* x   = (const float*)d_in[0];
    const int*   ei  = (const int*)  d_in[1];
    const float* W1  = (const float*)d_in[2];
    const float* as1 = (const float*)d_in[3];
    const float* ad1 = (const float*)d_in[4];
    const float* b1  = (const float*)d_in[5];
    const float* W2  = (const float*)d_in[6];
    const float* as2 = (const float*)d_in[7];
    const float* ad2 = (const float*)d_in[8];
    const float* b2  = (const float*)d_in[9];
    const float* W3  = (const float*)d_in[10];
    const float* as3 = (const float*)d_in[11];
    const float* ad3 = (const float*)d_in[12];
    const float* b3  = (const float*)d_in[13];
    float* out = (float*)d_out;

    float *bufA, *bufB, *alpha, *asrc, *adst, *invs, *out3, *pooled;
    __nv_bfloat16 *Ah, *Al, *B1h, *B1l, *B2h, *B2l, *B3h, *B3l;
    cudaGetSymbolAddress((void**)&bufA,   g_bufA);
    cudaGetSymbolAddress((void**)&bufB,   g_bufB);
    cudaGetSymbolAddress((void**)&alpha,  g_alpha);
    cudaGetSymbolAddress((void**)&asrc,   g_asrc);
    cudaGetSymbolAddress((void**)&adst,   g_adst);
    cudaGetSymbolAddress((void**)&invs,   g_invs);
    cudaGetSymbolAddress((void**)&out3,   g_out3);
    cudaGetSymbolAddress((void**)&pooled, g_pooled);
    cudaGetSymbolAddress((void**)&Ah,  g_Ah);
    cudaGetSymbolAddress((void**)&Al,  g_Al);
    cudaGetSymbolAddress((void**)&B1h, g_B1h);
    cudaGetSymbolAddress((void**)&B1l, g_B1l);
    cudaGetSymbolAddress((void**)&B2h, g_B2h);
    cudaGetSymbolAddress((void**)&B2l, g_B2l);
    cudaGetSymbolAddress((void**)&B3h, g_B3h);
    cudaGetSymbolAddress((void**)&B3l, g_B3l);

    if (!s_init) {
        cudaFuncSetAttribute(gemm_mma_k, cudaFuncAttributeMaxDynamicSharedMemorySize, GSMEM);
        cudaStreamCreateWithFlags(&s_s2, cudaStreamNonBlocking);
        cudaStreamCreateWithFlags(&s_s3, cudaStreamNonBlocking);
        cudaStreamCreateWithFlags(&s_s4, cudaStreamNonBlocking);
        cudaEventCreateWithFlags(&s_e0,     cudaEventDisableTiming);
        cudaEventCreateWithFlags(&s_eGraph, cudaEventDisableTiming);
        cudaEventCreateWithFlags(&s_eW1,    cudaEventDisableTiming);
        cudaEventCreateWithFlags(&s_eW2,    cudaEventDisableTiming);
        cudaEventCreateWithFlags(&s_eW3,    cudaEventDisableTiming);
        cudaEventCreateWithFlags(&s_eG1,    cudaEventDisableTiming);
        cudaEventCreateWithFlags(&s_ePad,   cudaEventDisableTiming);
        cudaEventCreateWithFlags(&s_eAgg2,  cudaEventDisableTiming);
        cudaEventCreateWithFlags(&s_e3b,    cudaEventDisableTiming);
        cudaEventCreateWithFlags(&s_e3c,    cudaEventDisableTiming);
        cudaEventCreateWithFlags(&s_e3d,    cudaEventDisableTiming);
        s_init = true;
    }
    cudaStream_t s2 = s_s2, s3 = s_s3, s4 = s_s4;

    const dim3 gemm_grid12((HC1 + 127) / 128, (NN + 127) / 128);   // 12 x 79
    const dim3 gemm_grid3 (1, (NN + 127) / 128);
    const int sm_blocks1 = (NN * H1 + 255) / 256;
    const int sm_blocks3 = (NN * H3 + 255) / 256;
    const dim3 agg_grid((HC1 / 4 + 127) / 128, NN);
    const dim3 convw_block(32, 8);

    cudaEventRecord(s_e0, 0);
    cudaStreamWaitEvent(s2, s_e0, 0);
    cudaStreamWaitEvent(s3, s_e0, 0);
    cudaStreamWaitEvent(s4, s_e0, 0);

    // keep the layer-1 GEMM as the 4th submitted launch for ncu
    {
        dim3 cwg1((HC1 + 31) / 32, (FIN + 31) / 32);
        conv_w_k<<<cwg1, convw_block, 0, s3>>>(W1, B1h, B1l, FIN, HC1, FIN);      // #1
        cudaEventRecord(s_eW1, s3);
    }
    conv_act_k<<<(NN * FIN + 255) / 256, 256>>>(x, Ah, Al, asrc, adst, FIN, FIN, NN); // #2
    {
        dim3 cwg2((HC1 + 31) / 32, (KPAD2 + 31) / 32);
        conv_w_k<<<cwg2, convw_block, 0, s3>>>(W2, B2h, B2l, HC1, HC1, KPAD2);    // #3
        cudaEventRecord(s_eW2, s3);
    }
    cudaStreamWaitEvent(0, s_eW1, 0);
    gemm_mma_k<<<gemm_grid12, 256, GSMEM>>>(Ah, Al, B1h, B1l, bufA, NN, HC1, FIN, // #4
                                            0, FIN / 32, as1, ad1, asrc, adst, H1);
    cudaEventRecord(s_eG1, 0);

    {
        dim3 cwg3((HC3 + 31) / 32, (KPAD2 + 31) / 32);
        conv_w_k<<<cwg3, convw_block, 0, s3>>>(W3, B3h, B3l, HC1, HC3, KPAD2);    // #5
        cudaEventRecord(s_eW3, s3);
    }

    // s2: graph build, concurrent with gemm1
    detect_fmt_k<<<1, 1, 0, s2>>>(ei);
    zero_deg_k<<<(NN + 255) / 256, 256, 0, s2>>>();
    build_edges_k<<<(ETOT + 255) / 256, 256, 0, s2>>>(ei);
    scan_k<<<1, 1024, 0, s2>>>();
    fill_csr_k<<<(ETOT + 255) / 256, 256, 0, s2>>>();
    cudaEventRecord(s_eGraph, s2);

    cudaStreamWaitEvent(s3, s_eG1, 0);
    zero_pad_k<<<(NN * (KPAD2 - HC1) + 255) / 256, 256, 0, s3>>>(Ah, Al);
    cudaEventRecord(s_ePad, s3);

    // layer 1
    cudaStreamWaitEvent(0, s_eGraph, 0);
    edge_softmax_k<<<sm_blocks1, 256>>>(asrc, adst, alpha, invs, H1);
    aggregate_k<<<agg_grid, 128>>>(bufA, alpha, invs, nullptr, b1, bufB, Ah, Al,
                                   asrc, adst, H1, HID);

    // layer 2
    cudaStreamWaitEvent(0, s_eW2, 0);
    cudaStreamWaitEvent(0, s_ePad, 0);
    gemm_mma_k<<<gemm_grid12, 256, GSMEM>>>(Ah, Al, B2h, B2l, bufA, NN, HC1, KPAD2,
                                            0, KPAD2 / 32, as2, ad2, asrc, adst, H1);
    edge_softmax_k<<<sm_blocks1, 256>>>(asrc, adst, alpha, invs, H1);
    aggregate_k<<<agg_grid, 128>>>(bufA, alpha, invs, bufB, b2, nullptr, Ah, Al,
                                   nullptr, nullptr, H1, HID);
    cudaEventRecord(s_eAgg2, 0);

    // layer 3: split-K x4
    float* part0 = bufB;
    float* part1 = bufB + 1 * (size_t)NN * HC3;
    float* part2 = bufB + 2 * (size_t)NN * HC3;
    float* part3 = bufB + 3 * (size_t)NN * HC3;
    const int KQ = KPAD2 / 4;
    cudaStreamWaitEvent(s2, s_eAgg2, 0);
    cudaStreamWaitEvent(s3, s_eAgg2, 0);
    cudaStreamWaitEvent(s4, s_eAgg2, 0);
    cudaStreamWaitEvent(s2, s_eW3, 0);
    cudaStreamWaitEvent(s3, s_eW3, 0);
    cudaStreamWaitEvent(s4, s_eW3, 0);
    cudaStreamWaitEvent(0,  s_eW3, 0);
    gemm_mma_k<<<gemm_grid3, 256, GSMEM, s2>>>(Ah, Al, B3h, B3l, part1, NN, HC3, KPAD2,
                                               1 * KQ, KQ / 32, nullptr, nullptr, nullptr, nullptr, 0);
    cudaEventRecord(s_e3b, s2);
    gemm_mma_k<<<gemm_grid3, 256, GSMEM, s3>>>(Ah, Al, B3h, B3l, part2, NN, HC3, KPAD2,
                                               2 * KQ, KQ / 32, nullptr, nullptr, nullptr, nullptr, 0);
    cudaEventRecord(s_e3c, s3);
    gemm_mma_k<<<gemm_grid3, 256, GSMEM, s4>>>(Ah, Al, B3h, B3l, part3, NN, HC3, KPAD2,
                                               3 * KQ, KQ / 32, nullptr, nullptr, nullptr, nullptr, 0);
    cudaEventRecord(s_e3d, s4);
    gemm_mma_k<<<gemm_grid3, 256, GSMEM>>>(Ah, Al, B3h, B3l, part0, NN, HC3, KPAD2,
                                           0, KQ / 32, nullptr, nullptr, nullptr, nullptr, 0);
    cudaStreamWaitEvent(0, s_e3b, 0);
    cudaStreamWaitEvent(0, s_e3c, 0);
    cudaStreamWaitEvent(0, s_e3d, 0);
    add4_dots_k<<<NN, 128>>>(part0, part1, part2, part3, bufA, as3, ad3, asrc, adst);

    edge_softmax_k<<<sm_blocks3, 256>>>(asrc, adst, alpha, invs, H3);
    aggregate3_k<<<NN, 64>>>(bufA, alpha, invs, b3, out3);

    colsum_k<<<NCLS, 256>>>(out3, pooled);
    finalize_k<<<1, 32>>>(pooled, out);
}